// round 2
// baseline (speedup 1.0000x reference)
#include <cuda_runtime.h>
#include <math.h>

#define FULLMASK 0xffffffffu
#define NS   25
#define NF   216
#define TLEN 2048

// ---------------- static device storage (no allocation) ----------------
__device__ __align__(16) float g_BT[NF * 32];     // B^T, padded: [flat][state(32)]
__device__ __align__(16) float g_EdgeVal[32 * 4]; // per-state in-edge A values
__device__ float g_I[32];                         // initial distribution

// In-edge source lanes per state (padded with self; padded coeff forced to 0)
__constant__ __align__(16) int c_srcTab[32 * 4] = {
    0,0,0,0,     0,1,1,1,     1,2,2,2,     2,3,3,3,
    3,16,4,4,    4,5,5,5,     5,6,6,6,     6,19,3,7,
    7,8,8,8,     8,9,9,9,     9,22,3,6,    10,11,11,11,
    11,12,12,12, 12,13,13,13, 3,16,14,14,  14,15,15,15,
    15,16,16,16, 6,19,17,17,  17,18,18,18, 18,19,19,19,
    9,22,20,20,  20,21,21,21, 21,22,22,22, 13,23,23,23,
    23,24,24,24, 25,25,25,25, 26,26,26,26, 27,27,27,27,
    28,28,28,28, 29,29,29,29, 30,30,30,30, 31,31,31,31
};
__constant__ int c_deg[32] = {1,1,1,1,2,1,1,3,1,1,4,1,1,2,2,1,1,2,1,1,2,1,1,2,2,0,0,0,0,0,0,0};

// Emission-spec "add" calls: {state, e0,e1,e2, xp, trainable, k_start}
// letters: 0=A 1=C 2=G 3=T 10=N 5=X ; ems already pad/truncated to 3 chars.
// k_starts precomputed from entry counts: NNNxp0=84, NNA=21, NAT=6, TGN=12,
// GNN=36, NNTxp2=16, NTA/NTG=4, NNNxp2=64, NNX=16, NXX=4.
__constant__ int c_adds[29][7] = {
    { 0, 10,10,10, 0,1,    0},
    { 1, 10,10, 0, 0,1,   84},
    { 2, 10, 0, 3, 0,1,  105},
    { 3,  0, 3, 2, 0,0,    0},
    { 4,  3, 2,10, 0,1,  111},
    { 5,  2,10,10, 0,1,  123},
    { 6, 10,10,10, 0,1,  159},
    { 7, 10,10,10, 0,1,  243},
    { 8, 10,10,10, 0,1,  327},
    { 9, 10,10,10, 0,1,  411},
    {10, 10,10, 3, 2,1,  495},
    {11, 10, 3, 0, 2,1,  511},
    {11, 10, 3, 2, 2,1,  515},
    {12,  3, 0, 0, 2,0,    0},
    {12,  3, 0, 2, 2,0,    0},
    {12,  3, 2, 0, 2,0,    0},
    {13, 10,10,10, 2,1,  519},
    {14, 10,10,10, 0,1,  583},
    {15, 10,10,10, 0,1,  667},
    {16, 10,10,10, 0,1,  751},
    {17, 10,10,10, 0,1,  835},
    {18, 10,10,10, 0,1,  919},
    {19, 10,10,10, 0,1, 1003},
    {20, 10,10,10, 0,1, 1087},
    {21, 10,10,10, 0,1, 1171},
    {22, 10,10,10, 0,1, 1255},
    {23, 10,10, 5, 2,1, 1339},
    {23, 10, 5, 5, 2,1, 1355},
    {24,  5, 5, 5, 2,0,    0}
};

// ---------------- setup: build A (sparse values), B^T, I ----------------
__device__ __forceinline__ int codeList(int ch, int* o) {
    if (ch == 10) { o[0]=0; o[1]=1; o[2]=2; o[3]=3; return 4; }
    o[0] = ch; return 1;
}

__device__ void addB(float* sB, const float* w,
                     int state, int e0, int e1, int e2,
                     int xp, int trainable, int k)
{
    int a0[6], a1[6], a2[6];
    int n0 = codeList(e0, a0);
    int n1 = codeList(e1, a1);
    int n2 = codeList(e2, a2);
    if (xp == 0) { a0[n0++] = 4; a1[n1++] = 4; }  // i < ORDER-xp for i=0,1
    int t = 0;
    for (int i0 = 0; i0 < n0; i0++) { int c0 = a0[i0];
        for (int i1 = 0; i1 < n1; i1++) { int c1 = a1[i1];
            if (c0 != 4 && c1 == 4) continue;      // 4 may not follow a non-4
            for (int i2 = 0; i2 < n2; i2++) { int c2 = a2[i2];
                sB[state*NF + c0*36 + c1*6 + c2] = trainable ? w[k + t] : 1.0f;
                t++;
            }
        }
    }
}

__global__ void setup_kernel(const float* __restrict__ tw,
                             const float* __restrict__ ew,
                             const float* __restrict__ iw)
{
    __shared__ float sA[25 * 25];
    __shared__ float sB[25 * NF];
    int tid = threadIdx.x;

    for (int i = tid; i < 25*25; i += 256) sA[i] = -1e30f;
    for (int i = tid; i < 25*NF; i += 256) sB[i] = -1e30f;
    __syncthreads();

    // B logits: 29 independent adds in parallel (disjoint cells)
    if (tid < 29) {
        const int* d = c_adds[tid];
        addB(sB, ew, d[0], d[1], d[2], d[3], d[4], d[5], d[6]);
    }
    // A logits (37 entries)
    if (tid == 32) {
        float w0=tw[0],w1=tw[1],w2=tw[2],w3=tw[3],w4=tw[4];
        float w5=tw[5],w6=tw[6],w7=tw[7],w8=tw[8],w9=tw[9];
        sA[0*25+0]=1.f-w0; sA[0*25+1]=w0;
        sA[1*25+2]=1.f;    sA[2*25+3]=1.f;
        sA[3*25+4]=w1;     sA[6*25+7]=w2;
        sA[4*25+5]=1.f;    sA[7*25+8]=1.f;
        sA[5*25+6]=1.f;    sA[8*25+9]=1.f;
        sA[3*25+14]=w3;    sA[6*25+17]=w4;   sA[9*25+20]=w5;
        sA[9*25+10]=1.f-w5;
        sA[14*25+15]=1.f;  sA[17*25+18]=1.f; sA[20*25+21]=1.f;
        sA[15*25+16]=1.f;  sA[18*25+19]=1.f; sA[21*25+22]=1.f;
        sA[16*25+4]=w6;    sA[19*25+7]=w7;   sA[22*25+10]=w8;
        sA[16*25+14]=1.f-w6; sA[19*25+17]=1.f-w7; sA[22*25+20]=1.f-w8;
        sA[3*25+7]=1.f - w9*w9;
        sA[3*25+10]=1.f - w9*w9*w9;
        sA[6*25+10]=1.f - w9*w9;
        sA[10*25+11]=1.f; sA[11*25+12]=1.f; sA[12*25+13]=1.f;
        sA[13*25+13]=1.f; sA[13*25+23]=1.f;
        sA[23*25+23]=1.f; sA[23*25+24]=1.f; sA[24*25+24]=1.f;
    }
    // I: softmax over first 9 weights
    if (tid == 64) {
        float mx = -1e30f;
        for (int i = 0; i < 9; i++) mx = fmaxf(mx, iw[i]);
        float v[9], sum = 0.f;
        for (int i = 0; i < 9; i++) { v[i] = expf(iw[i]-mx); sum += v[i]; }
        for (int i = 0; i < 9; i++) g_I[i] = v[i] / sum;
        for (int i = 9; i < 32; i++) g_I[i] = 0.f;
    }
    __syncthreads();

    // A row softmax (thread per row)
    if (tid < 25) {
        float mx = -1e30f;
        for (int j = 0; j < 25; j++) mx = fmaxf(mx, sA[tid*25+j]);
        float s = 0.f;
        for (int j = 0; j < 25; j++) { float v = expf(sA[tid*25+j]-mx); sA[tid*25+j]=v; s+=v; }
        float inv = 1.f / s;
        for (int j = 0; j < 25; j++) sA[tid*25+j] *= inv;
    }
    // B row softmax (warp per row)
    {
        int warp = tid >> 5, lane = tid & 31;
        for (int r = warp; r < 25; r += 8) {
            float mx = -1e30f;
            for (int c = lane; c < NF; c += 32) mx = fmaxf(mx, sB[r*NF+c]);
            for (int o = 16; o; o >>= 1) mx = fmaxf(mx, __shfl_xor_sync(FULLMASK, mx, o));
            float s = 0.f;
            for (int c = lane; c < NF; c += 32) { float v = expf(sB[r*NF+c]-mx); sB[r*NF+c]=v; s+=v; }
            for (int o = 16; o; o >>= 1) s += __shfl_xor_sync(FULLMASK, s, o);
            float inv = 1.f / s;
            for (int c = lane; c < NF; c += 32) sB[r*NF+c] *= inv;
        }
    }
    __syncthreads();

    // write B^T padded [flat][32] and per-edge A values
    for (int i = tid; i < NF*32; i += 256) {
        int f = i >> 5, s = i & 31;
        g_BT[i] = (s < 25) ? sB[s*NF + f] : 0.f;
    }
    for (int i = tid; i < 128; i += 256) {
        int j = i >> 2, r = i & 3;
        g_EdgeVal[i] = (j < 25 && r < c_deg[j]) ? sA[c_srcTab[i]*25 + j] : 0.f;
    }
}

// ---------------- forward kernel: warp per batch row ----------------
__global__ __launch_bounds__(128)
void hmm_forward(const int* __restrict__ tokens, float* __restrict__ out, int rows)
{
    __shared__ float shB[NF * 32];
    for (int i = threadIdx.x; i < NF*32; i += 128) shB[i] = g_BT[i];
    __syncthreads();

    const int lane = threadIdx.x & 31;
    const int row  = blockIdx.x * 4 + (threadIdx.x >> 5);
    if (row >= rows) return;
    const int* tok = tokens + (size_t)row * TLEN;

    const int4   sv = *(const int4*)  (&c_srcTab[lane*4]);
    const float4 ev = *(const float4*)(&g_EdgeVal[lane*4]);
    const int   s0 = sv.x, s1 = sv.y, s2 = sv.z, s3 = sv.w;
    const float v0 = ev.x, v1 = ev.y, v2 = ev.z, v3 = ev.w;

    // t = 0: alpha = I * E[0]; context (4,4,tok0) -> flat = 168 + tok0
    float a;
    {
        int f0 = 168 + tok[0];
        a = g_I[lane] * shB[(f0 << 5) + lane];
    }
    int expsum = 0;

    // tokens for first tile (t = 1..32), lane l handles t = t0 + l
    int tm2, tm1, tc;
    {
        int t = 1 + lane;
        tm2 = (t >= 2) ? tok[t-2] : 4;
        tm1 = tok[t-1];
        tc  = tok[t];
    }

    for (int t0 = 1; t0 < TLEN; t0 += 32) {
        int flatv = tm2*36 + tm1*6 + tc;
        int n = TLEN - t0; if (n > 32) n = 32;

        // prefetch next tile's tokens (hidden under this tile's 32 steps)
        int nt0 = t0 + 32;
        if (nt0 < TLEN) {
            int t = nt0 + lane;
            if (t < TLEN) { tm2 = tok[t-2]; tm1 = tok[t-1]; tc = tok[t]; }
        }

        #pragma unroll 8
        for (int i = 0; i < n; i++) {
            int   f  = __shfl_sync(FULLMASK, flatv, i);
            float e  = shB[(f << 5) + lane];
            float x0 = __shfl_sync(FULLMASK, a, s0);
            float x1 = __shfl_sync(FULLMASK, a, s1);
            float x2 = __shfl_sync(FULLMASK, a, s2);
            float x3 = __shfl_sync(FULLMASK, a, s3);
            // fold emission into coefficients while shuffles are in flight
            float w0 = v0*e, w1 = v1*e, w2 = v2*e, w3 = v3*e;
            a = fmaf(x0, w0, x1*w1) + fmaf(x2, w2, x3*w3);

            // exact power-of-2 rescale every 8 steps (no rounding error)
            if ((i & 7) == 7) {
                int m = __reduce_max_sync(FULLMASK, (__float_as_int(a) >> 23) & 255);
                a *= __int_as_float((254 - m) << 23);   // * 2^(127 - m)
                expsum += m - 127;
            }
        }
    }

    // final: ll = log(sum alpha) + expsum * ln2
    float s = a;
    #pragma unroll
    for (int o = 16; o; o >>= 1) s += __shfl_xor_sync(FULLMASK, s, o);
    if (lane == 0)
        out[row] = logf(s) + 0.6931471805599453f * (float)expsum;
}

// ---------------- entry point ----------------
extern "C" void kernel_launch(void* const* d_in, const int* in_sizes, int n_in,
                              void* d_out, int out_size)
{
    const float* tw     = (const float*)d_in[0];  // transition_kernel (10)
    const float* ew     = (const float*)d_in[1];  // emission_kernel (5400)
    const float* iw     = (const float*)d_in[2];  // init_kernel (25)
    const int*   tokens = (const int*)  d_in[3];  // (rows, 2048)
    float*       out    = (float*)d_out;

    int rows = in_sizes[3] / TLEN;

    setup_kernel<<<1, 256>>>(tw, ew, iw);
    hmm_forward<<<(rows + 3) / 4, 128>>>(tokens, out, rows);
}

// round 3
// speedup vs baseline: 1.3207x; 1.3207x over previous
#include <cuda_runtime.h>
#include <math.h>

#define FULLMASK 0xffffffffu
#define NS   25
#define NF   216
#define TLEN 2048

// ---------------- constant tables ----------------
// 1-step in-edge source lanes per state (padded with self; padded coeff -> 0)
__constant__ __align__(16) int c_srcTab[32 * 4] = {
    0,0,0,0,     0,1,1,1,     1,2,2,2,     2,3,3,3,
    3,16,4,4,    4,5,5,5,     5,6,6,6,     6,19,3,7,
    7,8,8,8,     8,9,9,9,     9,22,3,6,    10,11,11,11,
    11,12,12,12, 12,13,13,13, 3,16,14,14,  14,15,15,15,
    15,16,16,16, 6,19,17,17,  17,18,18,18, 18,19,19,19,
    9,22,20,20,  20,21,21,21, 21,22,22,22, 13,23,23,23,
    23,24,24,24, 25,25,25,25, 26,26,26,26, 27,27,27,27,
    28,28,28,28, 29,29,29,29, 30,30,30,30, 31,31,31,31
};
__constant__ int c_deg[32] = {1,1,1,1,2,1,1,3,1,1,4,1,1,2,2,1,1,2,1,1,2,1,1,2,2,0,0,0,0,0,0,0};

// true predecessor lists (for on-device 2-step path enumeration)
__constant__ int c_pred[25][4] = {
    {0,0,0,0},{0,0,0,0},{1,0,0,0},{2,0,0,0},{3,16,0,0},{4,0,0,0},{5,0,0,0},
    {6,19,3,0},{7,0,0,0},{8,0,0,0},{9,22,3,6},{10,0,0,0},{11,0,0,0},{12,13,0,0},
    {3,16,0,0},{14,0,0,0},{15,0,0,0},{6,19,0,0},{17,0,0,0},{18,0,0,0},
    {9,22,0,0},{20,0,0,0},{21,0,0,0},{13,23,0,0},{23,24,0,0}
};
__constant__ int c_pcnt[25] = {1,1,1,1,2,1,1,3,1,1,4,1,1,2,2,1,1,2,1,1,2,1,1,2,2};

// Emission-spec "add" calls: {state, e0,e1,e2, xp, trainable, k_start}
__constant__ int c_adds[29][7] = {
    { 0, 10,10,10, 0,1,    0},
    { 1, 10,10, 0, 0,1,   84},
    { 2, 10, 0, 3, 0,1,  105},
    { 3,  0, 3, 2, 0,0,    0},
    { 4,  3, 2,10, 0,1,  111},
    { 5,  2,10,10, 0,1,  123},
    { 6, 10,10,10, 0,1,  159},
    { 7, 10,10,10, 0,1,  243},
    { 8, 10,10,10, 0,1,  327},
    { 9, 10,10,10, 0,1,  411},
    {10, 10,10, 3, 2,1,  495},
    {11, 10, 3, 0, 2,1,  511},
    {11, 10, 3, 2, 2,1,  515},
    {12,  3, 0, 0, 2,0,    0},
    {12,  3, 0, 2, 2,0,    0},
    {12,  3, 2, 0, 2,0,    0},
    {13, 10,10,10, 2,1,  519},
    {14, 10,10,10, 0,1,  583},
    {15, 10,10,10, 0,1,  667},
    {16, 10,10,10, 0,1,  751},
    {17, 10,10,10, 0,1,  835},
    {18, 10,10,10, 0,1,  919},
    {19, 10,10,10, 0,1, 1003},
    {20, 10,10,10, 0,1, 1087},
    {21, 10,10,10, 0,1, 1171},
    {22, 10,10,10, 0,1, 1255},
    {23, 10,10, 5, 2,1, 1339},
    {23, 10, 5, 5, 2,1, 1355},
    {24,  5, 5, 5, 2,0,    0}
};

// ---------------- helpers ----------------
__device__ __forceinline__ int codeList(int ch, int* o) {
    if (ch == 10) { o[0]=0; o[1]=1; o[2]=2; o[3]=3; return 4; }
    o[0] = ch; return 1;
}

// writes directly into transposed padded layout shB[flat*32 + state]
__device__ void addB(float* shB, const float* w,
                     int state, int e0, int e1, int e2,
                     int xp, int trainable, int k)
{
    int a0[6], a1[6], a2[6];
    int n0 = codeList(e0, a0);
    int n1 = codeList(e1, a1);
    int n2 = codeList(e2, a2);
    if (xp == 0) { a0[n0++] = 4; a1[n1++] = 4; }
    int t = 0;
    for (int i0 = 0; i0 < n0; i0++) { int c0 = a0[i0];
        for (int i1 = 0; i1 < n1; i1++) { int c1 = a1[i1];
            if (c0 != 4 && c1 == 4) continue;
            for (int i2 = 0; i2 < n2; i2++) { int c2 = a2[i2];
                shB[((c0*36 + c1*6 + c2) << 5) + state] = trainable ? w[k + t] : 1.0f;
                t++;
            }
        }
    }
}

// ---------------- fused kernel: per-block setup + warp-per-row scan ----------------
__global__ __launch_bounds__(128)
void hmm_fused(const float* __restrict__ tw,
               const float* __restrict__ ew,
               const float* __restrict__ iw,
               const int* __restrict__ tokens,
               float* __restrict__ out, int rows)
{
    __shared__ float shB[NF * 32];   // B^T padded: [flat][state(32)]
    __shared__ float sA[25 * 25];
    __shared__ float sI[32];
    const int tid = threadIdx.x;

    // ---- init ----
    for (int i = tid; i < NF*32; i += 128) shB[i] = ((i & 31) < 25) ? -1e30f : 0.0f;
    for (int i = tid; i < 25*25;  i += 128) sA[i] = -1e30f;
    __syncthreads();

    // ---- B logits (29 disjoint adds) ----
    if (tid < 29) {
        const int* d = c_adds[tid];
        addB(shB, ew, d[0], d[1], d[2], d[3], d[4], d[5], d[6]);
    }
    // ---- A logits ----
    if (tid == 32) {
        float w0=tw[0],w1=tw[1],w2=tw[2],w3=tw[3],w4=tw[4];
        float w5=tw[5],w6=tw[6],w7=tw[7],w8=tw[8],w9=tw[9];
        sA[0*25+0]=1.f-w0; sA[0*25+1]=w0;
        sA[1*25+2]=1.f;    sA[2*25+3]=1.f;
        sA[3*25+4]=w1;     sA[6*25+7]=w2;
        sA[4*25+5]=1.f;    sA[7*25+8]=1.f;
        sA[5*25+6]=1.f;    sA[8*25+9]=1.f;
        sA[3*25+14]=w3;    sA[6*25+17]=w4;   sA[9*25+20]=w5;
        sA[9*25+10]=1.f-w5;
        sA[14*25+15]=1.f;  sA[17*25+18]=1.f; sA[20*25+21]=1.f;
        sA[15*25+16]=1.f;  sA[18*25+19]=1.f; sA[21*25+22]=1.f;
        sA[16*25+4]=w6;    sA[19*25+7]=w7;   sA[22*25+10]=w8;
        sA[16*25+14]=1.f-w6; sA[19*25+17]=1.f-w7; sA[22*25+20]=1.f-w8;
        sA[3*25+7]=1.f - w9*w9;
        sA[3*25+10]=1.f - w9*w9*w9;
        sA[6*25+10]=1.f - w9*w9;
        sA[10*25+11]=1.f; sA[11*25+12]=1.f; sA[12*25+13]=1.f;
        sA[13*25+13]=1.f; sA[13*25+23]=1.f;
        sA[23*25+23]=1.f; sA[23*25+24]=1.f; sA[24*25+24]=1.f;
    }
    // ---- I softmax (9 entries) ----
    if (tid == 64) {
        float mx = -1e30f;
        for (int i = 0; i < 9; i++) mx = fmaxf(mx, iw[i]);
        float v[9], sum = 0.f;
        for (int i = 0; i < 9; i++) { v[i] = expf(iw[i]-mx); sum += v[i]; }
        for (int i = 0; i < 9; i++) sI[i] = v[i] / sum;
        for (int i = 9; i < 32; i++) sI[i] = 0.f;
    }
    __syncthreads();

    // ---- A row softmax (thread per row) ----
    if (tid < 25) {
        float mx = -1e30f;
        for (int j = 0; j < 25; j++) mx = fmaxf(mx, sA[tid*25+j]);
        float s = 0.f;
        for (int j = 0; j < 25; j++) { float v = expf(sA[tid*25+j]-mx); sA[tid*25+j]=v; s+=v; }
        float inv = 1.f / s;
        for (int j = 0; j < 25; j++) sA[tid*25+j] *= inv;
    }
    // ---- B row softmax: thread per state, stride-32 column (bank-conflict-free) ----
    if (tid < 25) {
        const int s = tid;
        float mx = -1e30f;
        for (int f = 0; f < NF; f++) mx = fmaxf(mx, shB[(f<<5)+s]);
        float sum = 0.f;
        for (int f = 0; f < NF; f++) { float v = expf(shB[(f<<5)+s]-mx); shB[(f<<5)+s]=v; sum+=v; }
        float inv = 1.f / sum;
        for (int f = 0; f < NF; f++) shB[(f<<5)+s] *= inv;
    }
    __syncthreads();

    // ---- per-lane constants ----
    const int lane = tid & 31;

    // 2-step path table for this lane (j = lane): up to 4 paths (i -> k -> j)
    int   ps[4] = {0,0,0,0};
    int   pk[4] = {0,0,0,0};
    float pc[4] = {0.f,0.f,0.f,0.f};
    if (lane < 25) {
        int cnt = 0;
        for (int ki = 0; ki < c_pcnt[lane]; ki++) {
            int k = c_pred[lane][ki];
            float akj = sA[k*25 + lane];
            for (int ii = 0; ii < c_pcnt[k]; ii++) {
                int i = c_pred[k][ii];
                ps[cnt] = i; pk[cnt] = k;
                pc[cnt] = sA[i*25 + k] * akj;
                cnt++;
            }
        }
    }
    const int   S0 = ps[0], S1 = ps[1], S2 = ps[2], S3 = ps[3];
    const int   K0 = pk[0] , K1 = pk[1], K2 = pk[2], K3 = pk[3];
    const float C0 = pc[0], C1 = pc[1], C2 = pc[2], C3 = pc[3];

    // 1-step table (for the single t=1 step)
    const int u0 = c_srcTab[lane*4+0], u1 = c_srcTab[lane*4+1];
    const int u2 = c_srcTab[lane*4+2], u3 = c_srcTab[lane*4+3];
    const int dg = c_deg[lane];
    float v0 = (lane < 25 && dg > 0) ? sA[u0*25 + lane] : 0.f;
    float v1 = (lane < 25 && dg > 1) ? sA[u1*25 + lane] : 0.f;
    float v2 = (lane < 25 && dg > 2) ? sA[u2*25 + lane] : 0.f;
    float v3 = (lane < 25 && dg > 3) ? sA[u3*25 + lane] : 0.f;

    const int row = blockIdx.x * 4 + (tid >> 5);
    if (row >= rows) return;
    const int* tok = tokens + (size_t)row * TLEN;

    // ---- t = 0: alpha = I * E[0]; flat = 4*36 + 4*6 + tok0 ----
    const int tok0 = tok[0], tok1 = tok[1];
    float a = sI[lane] * shB[((168 + tok0) << 5) + lane];

    // ---- t = 1: single 1-step (flat = 4*36 + tok0*6 + tok1) ----
    {
        float e = shB[((144 + tok0*6 + tok1) << 5) + lane];
        float x0 = __shfl_sync(FULLMASK, a, u0);
        float x1 = __shfl_sync(FULLMASK, a, u1);
        float x2 = __shfl_sync(FULLMASK, a, u2);
        float x3 = __shfl_sync(FULLMASK, a, u3);
        a = (fmaf(x0, v0, x1*v1) + fmaf(x2, v2, x3*v3)) * e;
    }
    int expsum = 0;

    // ---- main loop: pairs (t, t+1), t = 2,4,...,2046  -> 1023 iterations ----
    // tile of 32 steps: lane l holds flat for step t0 + l; 16 pair-iters per tile
    int tm2, tm1, tc;
    {
        int t = 2 + lane;
        tm2 = tok[t-2]; tm1 = tok[t-1]; tc = tok[t];
    }

    for (int t0 = 2; t0 < TLEN; t0 += 32) {
        int flatv = tm2*36 + tm1*6 + tc;
        int nsteps = TLEN - t0; if (nsteps > 32) nsteps = 32;
        int niter = nsteps >> 1;

        // prefetch next tile's tokens
        int nt0 = t0 + 32;
        if (nt0 < TLEN) {
            int t = nt0 + lane;
            if (t < TLEN) { tm2 = tok[t-2]; tm1 = tok[t-1]; tc = tok[t]; }
        }

        #pragma unroll 4
        for (int i = 0; i < niter; i++) {
            int f0 = __shfl_sync(FULLMASK, flatv, 2*i);
            int f1 = __shfl_sync(FULLMASK, flatv, 2*i+1);
            const float* B0 = shB + (f0 << 5);
            float e1 = shB[(f1 << 5) + lane];
            // off-chain coefficient build
            float w0 = C0 * B0[K0] * e1;
            float w1 = C1 * B0[K1] * e1;
            float w2 = C2 * B0[K2] * e1;
            float w3 = C3 * B0[K3] * e1;
            // critical chain: 4 parallel shuffles + fma tree
            float x0 = __shfl_sync(FULLMASK, a, S0);
            float x1 = __shfl_sync(FULLMASK, a, S1);
            float x2 = __shfl_sync(FULLMASK, a, S2);
            float x3 = __shfl_sync(FULLMASK, a, S3);
            a = fmaf(x1, w1, x0*w0) + fmaf(x3, w3, x2*w2);

            // exact power-of-2 rescale every 4 iters (8 steps)
            if ((i & 3) == 3) {
                int m = __reduce_max_sync(FULLMASK, (__float_as_int(a) >> 23) & 255);
                a *= __int_as_float((254 - m) << 23);   // * 2^(127 - m)
                expsum += m - 127;
            }
        }
    }

    // ---- final: ll = log(sum alpha) + expsum * ln2 ----
    float s = a;
    #pragma unroll
    for (int o = 16; o; o >>= 1) s += __shfl_xor_sync(FULLMASK, s, o);
    if (lane == 0)
        out[row] = logf(s) + 0.6931471805599453f * (float)expsum;
}

// ---------------- entry point ----------------
extern "C" void kernel_launch(void* const* d_in, const int* in_sizes, int n_in,
                              void* d_out, int out_size)
{
    const float* tw     = (const float*)d_in[0];  // transition_kernel (10)
    const float* ew     = (const float*)d_in[1];  // emission_kernel (5400)
    const float* iw     = (const float*)d_in[2];  // init_kernel (25)
    const int*   tokens = (const int*)  d_in[3];  // (rows, 2048)
    float*       out    = (float*)d_out;

    int rows = in_sizes[3] / TLEN;

    hmm_fused<<<(rows + 3) / 4, 128>>>(tw, ew, iw, tokens, out, rows);
}

// round 4
// speedup vs baseline: 1.6581x; 1.2554x over previous
#include <cuda_runtime.h>
#include <math.h>

#define FULLMASK 0xffffffffu
#define NS   25
#define NF   216
#define TLEN 2048

// ---------------- constant tables ----------------
// 1-step in-edge source lanes per state (padded with self; padded coeff -> 0)
__constant__ __align__(16) int c_srcTab[32 * 4] = {
    0,0,0,0,     0,1,1,1,     1,2,2,2,     2,3,3,3,
    3,16,4,4,    4,5,5,5,     5,6,6,6,     6,19,3,7,
    7,8,8,8,     8,9,9,9,     9,22,3,6,    10,11,11,11,
    11,12,12,12, 12,13,13,13, 3,16,14,14,  14,15,15,15,
    15,16,16,16, 6,19,17,17,  17,18,18,18, 18,19,19,19,
    9,22,20,20,  20,21,21,21, 21,22,22,22, 13,23,23,23,
    23,24,24,24, 25,25,25,25, 26,26,26,26, 27,27,27,27,
    28,28,28,28, 29,29,29,29, 30,30,30,30, 31,31,31,31
};
__constant__ int c_deg[32] = {1,1,1,1,2,1,1,3,1,1,4,1,1,2,2,1,1,2,1,1,2,1,1,2,2,0,0,0,0,0,0,0};

// true predecessor lists (for on-device 2-step path enumeration)
__constant__ int c_pred[25][4] = {
    {0,0,0,0},{0,0,0,0},{1,0,0,0},{2,0,0,0},{3,16,0,0},{4,0,0,0},{5,0,0,0},
    {6,19,3,0},{7,0,0,0},{8,0,0,0},{9,22,3,6},{10,0,0,0},{11,0,0,0},{12,13,0,0},
    {3,16,0,0},{14,0,0,0},{15,0,0,0},{6,19,0,0},{17,0,0,0},{18,0,0,0},
    {9,22,0,0},{20,0,0,0},{21,0,0,0},{13,23,0,0},{23,24,0,0}
};
__constant__ int c_pcnt[25] = {1,1,1,1,2,1,1,3,1,1,4,1,1,2,2,1,1,2,1,1,2,1,1,2,2};

// Emission-spec "add" calls: {state, e0,e1,e2, xp, trainable, k_start}
__constant__ int c_adds[29][7] = {
    { 0, 10,10,10, 0,1,    0},
    { 1, 10,10, 0, 0,1,   84},
    { 2, 10, 0, 3, 0,1,  105},
    { 3,  0, 3, 2, 0,0,    0},
    { 4,  3, 2,10, 0,1,  111},
    { 5,  2,10,10, 0,1,  123},
    { 6, 10,10,10, 0,1,  159},
    { 7, 10,10,10, 0,1,  243},
    { 8, 10,10,10, 0,1,  327},
    { 9, 10,10,10, 0,1,  411},
    {10, 10,10, 3, 2,1,  495},
    {11, 10, 3, 0, 2,1,  511},
    {11, 10, 3, 2, 2,1,  515},
    {12,  3, 0, 0, 2,0,    0},
    {12,  3, 0, 2, 2,0,    0},
    {12,  3, 2, 0, 2,0,    0},
    {13, 10,10,10, 2,1,  519},
    {14, 10,10,10, 0,1,  583},
    {15, 10,10,10, 0,1,  667},
    {16, 10,10,10, 0,1,  751},
    {17, 10,10,10, 0,1,  835},
    {18, 10,10,10, 0,1,  919},
    {19, 10,10,10, 0,1, 1003},
    {20, 10,10,10, 0,1, 1087},
    {21, 10,10,10, 0,1, 1171},
    {22, 10,10,10, 0,1, 1255},
    {23, 10,10, 5, 2,1, 1339},
    {23, 10, 5, 5, 2,1, 1355},
    {24,  5, 5, 5, 2,0,    0}
};

// ---------------- helpers ----------------
__device__ __forceinline__ int codeList(int ch, int* o) {
    if (ch == 10) { o[0]=0; o[1]=1; o[2]=2; o[3]=3; return 4; }
    o[0] = ch; return 1;
}

// writes directly into transposed padded layout shB[flat*32 + state]
__device__ void addB(float* shB, const float* w,
                     int state, int e0, int e1, int e2,
                     int xp, int trainable, int k)
{
    int a0[6], a1[6], a2[6];
    int n0 = codeList(e0, a0);
    int n1 = codeList(e1, a1);
    int n2 = codeList(e2, a2);
    if (xp == 0) { a0[n0++] = 4; a1[n1++] = 4; }
    int t = 0;
    for (int i0 = 0; i0 < n0; i0++) { int c0 = a0[i0];
        for (int i1 = 0; i1 < n1; i1++) { int c1 = a1[i1];
            if (c0 != 4 && c1 == 4) continue;
            for (int i2 = 0; i2 < n2; i2++) { int c2 = a2[i2];
                shB[((c0*36 + c1*6 + c2) << 5) + state] = trainable ? w[k + t] : 1.0f;
                t++;
            }
        }
    }
}

// ---------------- fused kernel ----------------
__global__ __launch_bounds__(128)
void hmm_fused(const float* __restrict__ tw,
               const float* __restrict__ ew,
               const float* __restrict__ iw,
               const int* __restrict__ tokens,
               float* __restrict__ out, int rows)
{
    __shared__ float shB[NF * 32];   // B^T padded: [flat][state(32)]
    __shared__ float sA[25 * 25];
    __shared__ float sI[32];
    __shared__ float sRed[4 * 32];   // partial reductions for B softmax
    const int tid = threadIdx.x;

    // ---- init ----
    for (int i = tid; i < NF*32; i += 128) shB[i] = ((i & 31) < 25) ? -1e30f : 0.0f;
    for (int i = tid; i < 25*25;  i += 128) sA[i] = -1e30f;
    __syncthreads();

    // ---- B logits (29 disjoint adds) ----
    if (tid < 29) {
        const int* d = c_adds[tid];
        addB(shB, ew, d[0], d[1], d[2], d[3], d[4], d[5], d[6]);
    }
    // ---- A logits ----
    if (tid == 32) {
        float w0=tw[0],w1=tw[1],w2=tw[2],w3=tw[3],w4=tw[4];
        float w5=tw[5],w6=tw[6],w7=tw[7],w8=tw[8],w9=tw[9];
        sA[0*25+0]=1.f-w0; sA[0*25+1]=w0;
        sA[1*25+2]=1.f;    sA[2*25+3]=1.f;
        sA[3*25+4]=w1;     sA[6*25+7]=w2;
        sA[4*25+5]=1.f;    sA[7*25+8]=1.f;
        sA[5*25+6]=1.f;    sA[8*25+9]=1.f;
        sA[3*25+14]=w3;    sA[6*25+17]=w4;   sA[9*25+20]=w5;
        sA[9*25+10]=1.f-w5;
        sA[14*25+15]=1.f;  sA[17*25+18]=1.f; sA[20*25+21]=1.f;
        sA[15*25+16]=1.f;  sA[18*25+19]=1.f; sA[21*25+22]=1.f;
        sA[16*25+4]=w6;    sA[19*25+7]=w7;   sA[22*25+10]=w8;
        sA[16*25+14]=1.f-w6; sA[19*25+17]=1.f-w7; sA[22*25+20]=1.f-w8;
        sA[3*25+7]=1.f - w9*w9;
        sA[3*25+10]=1.f - w9*w9*w9;
        sA[6*25+10]=1.f - w9*w9;
        sA[10*25+11]=1.f; sA[11*25+12]=1.f; sA[12*25+13]=1.f;
        sA[13*25+13]=1.f; sA[13*25+23]=1.f;
        sA[23*25+23]=1.f; sA[23*25+24]=1.f; sA[24*25+24]=1.f;
    }
    // ---- I softmax (9 entries) ----
    if (tid == 64) {
        float mx = -1e30f;
        for (int i = 0; i < 9; i++) mx = fmaxf(mx, iw[i]);
        float v[9], sum = 0.f;
        for (int i = 0; i < 9; i++) { v[i] = expf(iw[i]-mx); sum += v[i]; }
        for (int i = 0; i < 9; i++) sI[i] = v[i] / sum;
        for (int i = 9; i < 32; i++) sI[i] = 0.f;
    }
    __syncthreads();

    // ---- A row softmax (thread per row) ----
    if (tid < 25) {
        float mx = -1e30f;
        for (int j = 0; j < 25; j++) mx = fmaxf(mx, sA[tid*25+j]);
        float s = 0.f;
        for (int j = 0; j < 25; j++) { float v = expf(sA[tid*25+j]-mx); sA[tid*25+j]=v; s+=v; }
        float inv = 1.f / s;
        for (int j = 0; j < 25; j++) sA[tid*25+j] *= inv;
    }
    // ---- B column softmax, 4-way parallel per state (conflict-free) ----
    {
        const int s  = tid & 31;     // state (lane) -> fixed bank per warp
        const int ch = tid >> 5;     // chunk 0..3, 54 flats each
        const int f0 = ch * 54, f1 = f0 + 54;
        float mx = -1e30f;
        for (int f = f0; f < f1; f++) mx = fmaxf(mx, shB[(f<<5)+s]);
        sRed[ch*32 + s] = mx;
        __syncthreads();
        mx = fmaxf(fmaxf(sRed[s], sRed[32+s]), fmaxf(sRed[64+s], sRed[96+s]));
        float sum = 0.f;
        for (int f = f0; f < f1; f++) {
            float v = __expf(shB[(f<<5)+s] - mx);
            shB[(f<<5)+s] = v; sum += v;
        }
        __syncthreads();
        sRed[ch*32 + s] = sum;
        __syncthreads();
        float tot = (sRed[s] + sRed[32+s]) + (sRed[64+s] + sRed[96+s]);
        float inv = 1.f / tot;
        for (int f = f0; f < f1; f++) shB[(f<<5)+s] *= inv;
    }
    __syncthreads();

    // ---- per-lane constants ----
    const int lane = tid & 31;

    // 2-step path table for this lane (j = lane): up to 4 paths (i -> k -> j)
    int   ps[4] = {0,0,0,0};
    int   pk[4];
    pk[0]=lane; pk[1]=lane; pk[2]=lane; pk[3]=lane;
    float pc[4] = {0.f,0.f,0.f,0.f};
    if (lane < 25) {
        int cnt = 0;
        for (int ki = 0; ki < c_pcnt[lane]; ki++) {
            int k = c_pred[lane][ki];
            float akj = sA[k*25 + lane];
            for (int ii = 0; ii < c_pcnt[k]; ii++) {
                int i = c_pred[k][ii];
                ps[cnt] = i; pk[cnt] = k;
                pc[cnt] = sA[i*25 + k] * akj;
                cnt++;
            }
        }
    }
    const int   S0 = ps[0], S1 = ps[1], S2 = ps[2], S3 = ps[3];
    const int   K0 = pk[0], K1 = pk[1], K2 = pk[2], K3 = pk[3];
    const float C0 = pc[0], C1 = pc[1], C2 = pc[2], C3 = pc[3];

    // 1-step table (t=1 and tail steps)
    const int u0 = c_srcTab[lane*4+0], u1 = c_srcTab[lane*4+1];
    const int u2 = c_srcTab[lane*4+2], u3 = c_srcTab[lane*4+3];
    const int dg = c_deg[lane];
    float v0 = (lane < 25 && dg > 0) ? sA[u0*25 + lane] : 0.f;
    float v1 = (lane < 25 && dg > 1) ? sA[u1*25 + lane] : 0.f;
    float v2 = (lane < 25 && dg > 2) ? sA[u2*25 + lane] : 0.f;
    float v3 = (lane < 25 && dg > 3) ? sA[u3*25 + lane] : 0.f;

    const int row = blockIdx.x * 4 + (tid >> 5);
    if (row >= rows) return;
    const int* tok = tokens + (size_t)row * TLEN;

    // ---- t = 0 ----
    const int tok0 = tok[0], tok1 = tok[1];
    float a = sI[lane] * shB[((168 + tok0) << 5) + lane];

    // ---- t = 1: single 1-step ----
    {
        float e = shB[((144 + tok0*6 + tok1) << 5) + lane];
        float x0 = __shfl_sync(FULLMASK, a, u0);
        float x1 = __shfl_sync(FULLMASK, a, u1);
        float x2 = __shfl_sync(FULLMASK, a, u2);
        float x3 = __shfl_sync(FULLMASK, a, u3);
        a = (fmaf(x0, v0, x1*v1) + fmaf(x2, v2, x3*v3)) * e;
    }
    int expsum = 0;

    // ---- main loop: 16-step tiles (8 pair-iters), t = 2 .. 2033 ----
    int tm2 = 0, tm1 = 0, tc = 0;
    if (lane < 16) { int t = 2 + lane; tm2 = tok[t-2]; tm1 = tok[t-1]; tc = tok[t]; }

    for (int t0 = 2; t0 <= 2018; t0 += 16) {
        int flatv = tm2*36 + tm1*6 + tc;

        // prefetch next tile's tokens
        int nt0 = t0 + 16;
        if (nt0 <= 2018 && lane < 16) {
            int t = nt0 + lane;
            tm2 = tok[t-2]; tm1 = tok[t-1]; tc = tok[t];
        }

        // stage emissions for all 16 steps (no dependence on alpha)
        float E[16];
        #pragma unroll
        for (int s = 0; s < 16; s++) {
            int f = __shfl_sync(FULLMASK, flatv, s);
            E[s] = shB[(f << 5) + lane];
        }

        float sc = 1.f; int pend = 0;
        #pragma unroll
        for (int i = 0; i < 8; i++) {
            // coefficient build: pure register ops, off the alpha chain
            float e1 = E[2*i+1];
            float q0 = __shfl_sync(FULLMASK, E[2*i], K0);
            float q1 = __shfl_sync(FULLMASK, E[2*i], K1);
            float q2 = __shfl_sync(FULLMASK, E[2*i], K2);
            float q3 = __shfl_sync(FULLMASK, E[2*i], K3);
            float w0 = C0*q0*e1, w1 = C1*q1*e1, w2 = C2*q2*e1, w3 = C3*q3*e1;
            // critical chain
            float x0 = __shfl_sync(FULLMASK, a, S0);
            float x1 = __shfl_sync(FULLMASK, a, S1);
            float x2 = __shfl_sync(FULLMASK, a, S2);
            float x3 = __shfl_sync(FULLMASK, a, S3);
            a = fmaf(x1, w1, x0*w0) + fmaf(x3, w3, x2*w2);

            // deferred exact power-of-2 rescale:
            // measure at i=2,6 (off-chain REDUX), apply at i=3,7 (one FFMA)
            if ((i & 3) == 2) {
                int m = __reduce_max_sync(FULLMASK, (__float_as_int(a) >> 23) & 255);
                sc = __int_as_float((254 - m) << 23);   // 2^(127-m)
                pend = m - 127;
            }
            if ((i & 3) == 3) {
                a *= sc;
                expsum += pend;
            }
        }
    }

    // ---- tail: t = 2034 .. 2047 (14 single steps) ----
    for (int t = 2034; t < TLEN; t++) {
        int f = tok[t-2]*36 + tok[t-1]*6 + tok[t];
        float e = shB[(f << 5) + lane];
        float x0 = __shfl_sync(FULLMASK, a, u0);
        float x1 = __shfl_sync(FULLMASK, a, u1);
        float x2 = __shfl_sync(FULLMASK, a, u2);
        float x3 = __shfl_sync(FULLMASK, a, u3);
        a = (fmaf(x0, v0, x1*v1) + fmaf(x2, v2, x3*v3)) * e;
        if (t == 2041) {
            int m = __reduce_max_sync(FULLMASK, (__float_as_int(a) >> 23) & 255);
            a *= __int_as_float((254 - m) << 23);
            expsum += m - 127;
        }
    }

    // ---- final: ll = log(sum alpha) + expsum * ln2 ----
    float s = a;
    #pragma unroll
    for (int o = 16; o; o >>= 1) s += __shfl_xor_sync(FULLMASK, s, o);
    if (lane == 0)
        out[row] = logf(s) + 0.6931471805599453f * (float)expsum;
}

// ---------------- entry point ----------------
extern "C" void kernel_launch(void* const* d_in, const int* in_sizes, int n_in,
                              void* d_out, int out_size)
{
    const float* tw     = (const float*)d_in[0];  // transition_kernel (10)
    const float* ew     = (const float*)d_in[1];  // emission_kernel (5400)
    const float* iw     = (const float*)d_in[2];  // init_kernel (25)
    const int*   tokens = (const int*)  d_in[3];  // (rows, 2048)
    float*       out    = (float*)d_out;

    int rows = in_sizes[3] / TLEN;

    hmm_fused<<<(rows + 3) / 4, 128>>>(tw, ew, iw, tokens, out, rows);
}